// round 5
// baseline (speedup 1.0000x reference)
#include <cuda_runtime.h>
#include <cuda_bf16.h>
#include <cstdint>

// ============================================================================
// Problem constants
// ============================================================================
#define B_DIM 8
#define N_DIM 4096
#define D_DIM 512
#define TILE  128
#define JTILES 32                  // 4096 / 128
#define NPANEL (B_DIM * (N_DIM / TILE))   // 256 CTAs
#define PD 4                       // cp.async pipeline depth (B chunks)

// SMEM: A panel 8 chunks x 16KB = 128KB, then PD B stages x 16KB
#define SM_B      131072
#define SMEM_BYTES (SM_B + PD * 16384)    // 196608

// Scratch (device globals — no cudaMalloc allowed)
__device__ __align__(16) __nv_bfloat16 g_xb[(size_t)B_DIM * N_DIM * D_DIM]; // 32 MB
__device__ float g_sq[B_DIM * N_DIM];
__device__ float g_inv[B_DIM * N_DIM];

// ============================================================================
// Helpers (base sm_103-safe PTX only: cp.async, ldmatrix, mma.sync)
// ============================================================================
__device__ __forceinline__ uint32_t smem_to_u32(const void* p) {
    uint32_t a;
    asm("{ .reg .u64 t; cvta.to.shared.u64 t, %1; cvt.u32.u64 %0, t; }" : "=r"(a) : "l"(p));
    return a;
}
#define SWZ(o) ((o) ^ (((o) >> 3) & 0x70))

__device__ __forceinline__ void cp_async16(uint32_t smem_addr, const void* gptr) {
    asm volatile("cp.async.cg.shared.global [%0], [%1], 16;" :: "r"(smem_addr), "l"(gptr) : "memory");
}
#define CP_COMMIT() asm volatile("cp.async.commit_group;" ::: "memory")
#define CP_WAIT3()  asm volatile("cp.async.wait_group 3;" ::: "memory")

__device__ __forceinline__ void ldm_x4(uint32_t* r, uint32_t addr) {
    asm volatile("ldmatrix.sync.aligned.m8n8.x4.shared.b16 {%0,%1,%2,%3}, [%4];"
                 : "=r"(r[0]), "=r"(r[1]), "=r"(r[2]), "=r"(r[3]) : "r"(addr));
}

__device__ __forceinline__ void mma16816(float* d, const uint32_t* a, const uint32_t* bq) {
    asm volatile(
        "mma.sync.aligned.m16n8k16.row.col.f32.bf16.bf16.f32 "
        "{%0,%1,%2,%3}, {%4,%5,%6,%7}, {%8,%9}, {%0,%1,%2,%3};"
        : "+f"(d[0]), "+f"(d[1]), "+f"(d[2]), "+f"(d[3])
        : "r"(a[0]), "r"(a[1]), "r"(a[2]), "r"(a[3]), "r"(bq[0]), "r"(bq[1]));
}

// Hyperbolic distance epilogue math (sqrt/lg2 via MUFU approx; |rel err| ~1e-6)
__device__ __forceinline__ float hypd(float gv, float sq_i, float rf_i, float sq_j, float inv_j) {
    float d2 = fmaf(-2.0f, gv, sq_i + sq_j);
    d2 = fmaxf(d2, 0.0f);
    float sd; asm("sqrt.approx.f32 %0, %1;" : "=f"(sd) : "f"(d2));
    float y   = sd * inv_j * rf_i;          // rf_i = 2 / (1 - ||x_i||^2)
    float arg = y + 1.0f;
    float t2  = fmaf(arg, arg, -1.0f);
    t2 = fmaxf(t2, 0.0f);
    float st; asm("sqrt.approx.f32 %0, %1;" : "=f"(st) : "f"(t2));
    float u = arg + st;
    float lg; asm("lg2.approx.f32 %0, %1;" : "=f"(lg) : "f"(u));
    return lg * 0.69314718055994531f;       // ln(2) * log2 = acosh(arg)
}

// ============================================================================
// Prep: fp32 -> bf16, per-row ||x||^2 and 1/(1-||x||^2).
// (inputs are in (-0.04,0.04): ||x|| <= 0.905 < 1, so __proj is identity)
// ============================================================================
__global__ void __launch_bounds__(256) hyp_prep(const float* __restrict__ emb) {
    const int rowid = blockIdx.x * 8 + (threadIdx.x >> 5);
    const int lane = threadIdx.x & 31;
    const float* src = emb + (size_t)rowid * D_DIM;
    __nv_bfloat16* dst = g_xb + (size_t)rowid * D_DIM;
    float ss = 0.0f;
#pragma unroll
    for (int k = 0; k < 4; ++k) {
        float4 v = reinterpret_cast<const float4*>(src)[lane + k * 32];
        ss = fmaf(v.x, v.x, ss); ss = fmaf(v.y, v.y, ss);
        ss = fmaf(v.z, v.z, ss); ss = fmaf(v.w, v.w, ss);
        union { __nv_bfloat162 h[2]; uint2 u; } cv;
        cv.h[0] = __floats2bfloat162_rn(v.x, v.y);
        cv.h[1] = __floats2bfloat162_rn(v.z, v.w);
        *reinterpret_cast<uint2*>(dst + lane * 4 + k * 128) = cv.u;
    }
#pragma unroll
    for (int o = 16; o > 0; o >>= 1) ss += __shfl_xor_sync(0xFFFFFFFFu, ss, o);
    if (lane == 0) {
        g_sq[rowid] = ss;
        g_inv[rowid] = 1.0f / (1.0f - ss);
    }
}

// ============================================================================
// Main: one CTA per (batch, 128-row i-panel). A panel resident in SMEM.
// 8 warps (4x2), warp tile 32x64, mma.sync m16n8k16 bf16, cp.async B ring.
// ============================================================================
__global__ void __launch_bounds__(256, 1) hyp_main(float* __restrict__ out) {
    extern __shared__ char smem[];
    const uint32_t sb = smem_to_u32(smem);
    const int tid  = threadIdx.x;
    const int lane = tid & 31;
    const int wid  = tid >> 5;
    const int wm   = wid >> 1;           // 0..3  (32-row slab)
    const int wn   = wid & 1;            // 0..1  (64-col slab)
    const int panel = blockIdx.x;
    const int b  = panel >> 5;
    const int i0 = (panel & 31) * TILE;

    const __nv_bfloat16* Abase = g_xb + ((size_t)(b * N_DIM + i0)) * D_DIM;
    const __nv_bfloat16* Bbase = g_xb + ((size_t)b * N_DIM) * D_DIM;

    // ---- prologue group 0: A panel 128 x 512 bf16 (8 chunks of 64 k-cols) ----
#pragma unroll
    for (int q = 0; q < 32; ++q) {
        int u  = tid + q * 256;          // 8192 16B units
        int r  = u >> 6;                 // row
        int t  = u & 63;                 // 16B unit within row
        int ck = t >> 3;                 // k-chunk
        int tc = t & 7;
        uint32_t dst = sb + ck * 16384 + SWZ(r * 128 + tc * 16);
        cp_async16(dst, Abase + (size_t)r * D_DIM + t * 8);
    }
    CP_COMMIT();
    // ---- B prologue: chunks 0..PD-1 (all within j-tile 0) ----
#pragma unroll
    for (int p = 0; p < PD; ++p) {
#pragma unroll
        for (int q = 0; q < 4; ++q) {
            int u = tid + q * 256;       // 1024 16B units per chunk
            int r = u >> 3, tc = u & 7;
            uint32_t dst = sb + SM_B + p * 16384 + SWZ(r * 128 + tc * 16);
            cp_async16(dst, Bbase + (size_t)r * D_DIM + p * 64 + tc * 8);
        }
        CP_COMMIT();
    }

    // ---- per-thread row constants ----
    float acc[2][8][4];
#pragma unroll
    for (int t = 0; t < 2; ++t)
#pragma unroll
        for (int u = 0; u < 8; ++u)
#pragma unroll
            for (int r = 0; r < 4; ++r) acc[t][u][r] = 0.0f;

    float sqi[2][2], rfi[2][2];
#pragma unroll
    for (int t = 0; t < 2; ++t)
#pragma unroll
        for (int g = 0; g < 2; ++g) {
            int r = i0 + wm * 32 + t * 16 + g * 8 + (lane >> 2);
            sqi[t][g] = g_sq[b * N_DIM + r];
            rfi[t][g] = 2.0f * g_inv[b * N_DIM + r];
        }

    int rowA[2], swA[2];
#pragma unroll
    for (int t = 0; t < 2; ++t) {
        rowA[t] = wm * 32 + t * 16 + (lane & 7) + ((lane >> 3) & 1) * 8;
        swA[t]  = (rowA[t] & 7) << 4;
    }
    int rowB[4], swB[4];
#pragma unroll
    for (int u2 = 0; u2 < 4; ++u2) {
        rowB[u2] = wn * 64 + u2 * 16 + (lane & 7) + (lane >> 4) * 8;
        swB[u2]  = (rowB[u2] & 7) << 4;
    }
    const int kaoff = (lane >> 4) * 16;         // bytes: A k-halves from lane bit 4
    const int kboff = ((lane >> 3) & 1) * 16;   // bytes: B k-halves from lane bit 3

    // ---- main loop: 256 chunks (32 j-tiles x 8 k-chunks) ----
    for (int cidx = 0; cidx < 256; ++cidx) {
        const int j = cidx >> 3, c = cidx & 7;
        CP_WAIT3();
        __syncthreads();

        const uint32_t ast = sb + c * 16384;
        const uint32_t bst = sb + SM_B + (cidx & (PD - 1)) * 16384;
#pragma unroll
        for (int s = 0; s < 4; ++s) {
            const int kb = s * 32;
            uint32_t afr[2][4];
#pragma unroll
            for (int t = 0; t < 2; ++t)
                ldm_x4(afr[t], ast + rowA[t] * 128 + ((kb + kaoff) ^ swA[t]));
            uint32_t bfr[4][4];
#pragma unroll
            for (int u2 = 0; u2 < 4; ++u2)
                ldm_x4(bfr[u2], bst + rowB[u2] * 128 + ((kb + kboff) ^ swB[u2]));
#pragma unroll
            for (int t = 0; t < 2; ++t)
#pragma unroll
                for (int u = 0; u < 8; ++u)
                    mma16816(acc[t][u], afr[t], &bfr[u >> 1][(u & 1) * 2]);
        }
        __syncthreads();

        // prefetch chunk cidx+PD into the stage we just drained
        const int nx = cidx + PD;
        if (nx < 256) {
            const int jn = nx >> 3, cn = nx & 7;
            const __nv_bfloat16* Bt = g_xb + ((size_t)(b * N_DIM + jn * TILE)) * D_DIM;
            const uint32_t stg = sb + SM_B + (nx & (PD - 1)) * 16384;
#pragma unroll
            for (int q = 0; q < 4; ++q) {
                int u = tid + q * 256;
                int r = u >> 3, tc = u & 7;
                cp_async16(stg + SWZ(r * 128 + tc * 16),
                           Bt + (size_t)r * D_DIM + cn * 64 + tc * 8);
            }
        }
        CP_COMMIT();   // commit (possibly empty) to keep wait_group counts aligned

        // ---- epilogue for finished j-tile (overlaps in-flight prefetches) ----
        if (c == 7) {
            const int j0 = j * TILE;
            const float* sqj  = g_sq  + b * N_DIM + j0;
            const float* invj = g_inv + b * N_DIM + j0;
#pragma unroll
            for (int u = 0; u < 8; ++u) {
                const int col = wn * 64 + u * 8 + (lane & 3) * 2;
                const float sq0 = __ldg(sqj + col),  sq1 = __ldg(sqj + col + 1);
                const float iv0 = __ldg(invj + col), iv1 = __ldg(invj + col + 1);
#pragma unroll
                for (int t = 0; t < 2; ++t)
#pragma unroll
                    for (int g = 0; g < 2; ++g) {
                        const int row = wm * 32 + t * 16 + g * 8 + (lane >> 2);
                        const int ig = i0 + row;
                        float d0 = hypd(acc[t][u][g * 2 + 0], sqi[t][g], rfi[t][g], sq0, iv0);
                        float d1 = hypd(acc[t][u][g * 2 + 1], sqi[t][g], rfi[t][g], sq1, iv1);
                        if (ig == j0 + col)     d0 = 0.0f;   // exact diagonal
                        if (ig == j0 + col + 1) d1 = 0.0f;
                        float2 v = make_float2(d0, d1);
                        *reinterpret_cast<float2*>(
                            out + ((size_t)(b * N_DIM) + ig) * N_DIM + j0 + col) = v;
                        acc[t][u][g * 2 + 0] = 0.0f;
                        acc[t][u][g * 2 + 1] = 0.0f;
                    }
            }
        }
    }
}

// ============================================================================
// Launch
// ============================================================================
extern "C" void kernel_launch(void* const* d_in, const int* in_sizes, int n_in,
                              void* d_out, int out_size) {
    (void)in_sizes; (void)n_in; (void)out_size;
    const float* emb = (const float*)d_in[0];
    float* out = (float*)d_out;
    cudaFuncSetAttribute(hyp_main, cudaFuncAttributeMaxDynamicSharedMemorySize, SMEM_BYTES);
    hyp_prep<<<(B_DIM * N_DIM) / 8, 256>>>(emb);
    hyp_main<<<NPANEL, 256, SMEM_BYTES>>>(out);
}

// round 6
// speedup vs baseline: 2.0119x; 2.0119x over previous
#include <cuda_runtime.h>
#include <cuda_bf16.h>
#include <cstdint>

// ============================================================================
// Problem constants
// ============================================================================
#define B_DIM 8
#define N_DIM 4096
#define D_DIM 512
#define TILE  128
#define NTILE (N_DIM / TILE)            // 32
#define PAIRS ((NTILE * (NTILE + 1)) / 2)  // 528 upper-triangular tile pairs
#define NCTA  (B_DIM * PAIRS)           // 4224 CTAs
#define NCHUNK 8                        // 512 / 64 K-chunks
#define PD 3                            // cp.async stages (A+B per stage)

// SMEM: 3 stages x (16KB A + 16KB B) = 96KB; transpose scratch reuses stage 0
#define STAGE_BYTES 32768
#define SMEM_BYTES (PD * STAGE_BYTES)   // 98304

// Scratch (device globals — no cudaMalloc allowed)
__device__ __align__(16) __nv_bfloat16 g_xb[(size_t)B_DIM * N_DIM * D_DIM]; // 32 MB
__device__ float g_sq[B_DIM * N_DIM];
__device__ float g_inv[B_DIM * N_DIM];

// ============================================================================
// Helpers (base sm_103-safe PTX only: cp.async, ldmatrix, mma.sync)
// ============================================================================
__device__ __forceinline__ uint32_t smem_to_u32(const void* p) {
    uint32_t a;
    asm("{ .reg .u64 t; cvta.to.shared.u64 t, %1; cvt.u32.u64 %0, t; }" : "=r"(a) : "l"(p));
    return a;
}
#define SWZ(o) ((o) ^ (((o) >> 3) & 0x70))

__device__ __forceinline__ void cp_async16(uint32_t smem_addr, const void* gptr) {
    asm volatile("cp.async.cg.shared.global [%0], [%1], 16;" :: "r"(smem_addr), "l"(gptr) : "memory");
}
#define CP_COMMIT() asm volatile("cp.async.commit_group;" ::: "memory")
#define CP_WAIT2()  asm volatile("cp.async.wait_group 2;" ::: "memory")

__device__ __forceinline__ void ldm_x4(uint32_t* r, uint32_t addr) {
    asm volatile("ldmatrix.sync.aligned.m8n8.x4.shared.b16 {%0,%1,%2,%3}, [%4];"
                 : "=r"(r[0]), "=r"(r[1]), "=r"(r[2]), "=r"(r[3]) : "r"(addr));
}

__device__ __forceinline__ void mma16816(float* d, const uint32_t* a, const uint32_t* bq) {
    asm volatile(
        "mma.sync.aligned.m16n8k16.row.col.f32.bf16.bf16.f32 "
        "{%0,%1,%2,%3}, {%4,%5,%6,%7}, {%8,%9}, {%0,%1,%2,%3};"
        : "+f"(d[0]), "+f"(d[1]), "+f"(d[2]), "+f"(d[3])
        : "r"(a[0]), "r"(a[1]), "r"(a[2]), "r"(a[3]), "r"(bq[0]), "r"(bq[1]));
}

// Hyperbolic distance epilogue math (sqrt/lg2 via MUFU approx)
__device__ __forceinline__ float hypd(float gv, float sq_i, float rf_i, float sq_j, float inv_j) {
    float d2 = fmaf(-2.0f, gv, sq_i + sq_j);
    d2 = fmaxf(d2, 0.0f);
    float sd; asm("sqrt.approx.f32 %0, %1;" : "=f"(sd) : "f"(d2));
    float y   = sd * inv_j * rf_i;          // rf_i = 2 / (1 - ||x_i||^2)
    float arg = y + 1.0f;
    float t2  = fmaf(arg, arg, -1.0f);
    t2 = fmaxf(t2, 0.0f);
    float st; asm("sqrt.approx.f32 %0, %1;" : "=f"(st) : "f"(t2));
    float u = arg + st;
    float lg; asm("lg2.approx.f32 %0, %1;" : "=f"(lg) : "f"(u));
    return lg * 0.69314718055994531f;       // acosh(arg)
}

// ============================================================================
// Prep: fp32 -> bf16, per-row ||x||^2 and 1/(1-||x||^2).
// (inputs are in (-0.04,0.04): ||x|| <= 0.905 < 1, so __proj is identity)
// ============================================================================
__global__ void __launch_bounds__(256) hyp_prep(const float* __restrict__ emb) {
    const int rowid = blockIdx.x * 8 + (threadIdx.x >> 5);
    const int lane = threadIdx.x & 31;
    const float* src = emb + (size_t)rowid * D_DIM;
    __nv_bfloat16* dst = g_xb + (size_t)rowid * D_DIM;
    float ss = 0.0f;
#pragma unroll
    for (int k = 0; k < 4; ++k) {
        float4 v = reinterpret_cast<const float4*>(src)[lane + k * 32];
        ss = fmaf(v.x, v.x, ss); ss = fmaf(v.y, v.y, ss);
        ss = fmaf(v.z, v.z, ss); ss = fmaf(v.w, v.w, ss);
        union { __nv_bfloat162 h[2]; uint2 u; } cv;
        cv.h[0] = __floats2bfloat162_rn(v.x, v.y);
        cv.h[1] = __floats2bfloat162_rn(v.z, v.w);
        *reinterpret_cast<uint2*>(dst + lane * 4 + k * 128) = cv.u;
    }
#pragma unroll
    for (int o = 16; o > 0; o >>= 1) ss += __shfl_xor_sync(0xFFFFFFFFu, ss, o);
    if (lane == 0) {
        g_sq[rowid] = ss;
        g_inv[rowid] = 1.0f / (1.0f - ss);
    }
}

// ============================================================================
// Main: one CTA per (batch, upper-triangular 128x128 tile pair).
// 16 warps (4x4 grid), warp tile 32x32, mma.sync m16n8k16 bf16.
// Triple-buffered cp.async for A+B K-chunks. Writes tile and its transpose.
// ============================================================================
__global__ void __launch_bounds__(512, 1) hyp_main(float* __restrict__ out) {
    extern __shared__ char smem[];
    const uint32_t sb = smem_to_u32(smem);
    const int tid  = threadIdx.x;
    const int lane = tid & 31;
    const int wid  = tid >> 5;
    const int wm   = wid >> 2;           // 0..3  (32-row slab)
    const int wn   = wid & 3;            // 0..3  (32-col slab)

    // ---- decode (batch, ti, tj) with ti <= tj; consecutive p share ti ----
    const int bx = blockIdx.x;
    const int b  = bx / PAIRS;
    int p = bx - b * PAIRS;
    int ti = 0;
    while (p >= NTILE - ti) { p -= NTILE - ti; ++ti; }
    const int tj = ti + p;
    const int i0 = ti * TILE;
    const int j0 = tj * TILE;

    const __nv_bfloat16* Abase = g_xb + ((size_t)(b * N_DIM + i0)) * D_DIM;
    const __nv_bfloat16* Bbase = g_xb + ((size_t)(b * N_DIM + j0)) * D_DIM;

    // ---- prologue: chunks 0..PD-1 (A+B per stage) ----
#pragma unroll
    for (int c = 0; c < PD; ++c) {
#pragma unroll
        for (int it = 0; it < 2; ++it) {
            int u = tid + it * 512;      // 1024 16B units per operand chunk
            int r = u >> 3, tc = u & 7;
            uint32_t sw = SWZ(r * 128 + tc * 16);
            cp_async16(sb + c * STAGE_BYTES + sw,
                       Abase + (size_t)r * D_DIM + c * 64 + tc * 8);
            cp_async16(sb + c * STAGE_BYTES + 16384 + sw,
                       Bbase + (size_t)r * D_DIM + c * 64 + tc * 8);
        }
        CP_COMMIT();
    }

    float acc[2][4][4];
#pragma unroll
    for (int t = 0; t < 2; ++t)
#pragma unroll
        for (int u = 0; u < 4; ++u)
#pragma unroll
            for (int r = 0; r < 4; ++r) acc[t][u][r] = 0.0f;

    // ldmatrix addressing (validated mapping from the passing round-5 kernel)
    int rowA[2], swA[2];
#pragma unroll
    for (int t = 0; t < 2; ++t) {
        rowA[t] = wm * 32 + t * 16 + (lane & 7) + ((lane >> 3) & 1) * 8;
        swA[t]  = (rowA[t] & 7) << 4;
    }
    int rowB[2], swB[2];
#pragma unroll
    for (int u2 = 0; u2 < 2; ++u2) {
        rowB[u2] = wn * 32 + u2 * 16 + (lane & 7) + (lane >> 4) * 8;
        swB[u2]  = (rowB[u2] & 7) << 4;
    }
    const int kaoff = (lane >> 4) * 16;
    const int kboff = ((lane >> 3) & 1) * 16;

    // ---- K loop: 8 chunks of 64 ----
    for (int c = 0; c < NCHUNK; ++c) {
        CP_WAIT2();
        __syncthreads();
        const uint32_t ast = sb + (c % PD) * STAGE_BYTES;
        const uint32_t bst = ast + 16384;
#pragma unroll
        for (int s = 0; s < 4; ++s) {
            const int kb = s * 32;
            uint32_t afr[2][4];
#pragma unroll
            for (int t = 0; t < 2; ++t)
                ldm_x4(afr[t], ast + rowA[t] * 128 + ((kb + kaoff) ^ swA[t]));
            uint32_t bfr[2][4];
#pragma unroll
            for (int u2 = 0; u2 < 2; ++u2)
                ldm_x4(bfr[u2], bst + rowB[u2] * 128 + ((kb + kboff) ^ swB[u2]));
#pragma unroll
            for (int t = 0; t < 2; ++t)
#pragma unroll
                for (int u = 0; u < 4; ++u)
                    mma16816(acc[t][u], afr[t], &bfr[u >> 1][(u & 1) * 2]);
        }
        __syncthreads();
        const int nx = c + PD;
        if (nx < NCHUNK) {
            const uint32_t stg = sb + (nx % PD) * STAGE_BYTES;
#pragma unroll
            for (int it = 0; it < 2; ++it) {
                int u = tid + it * 512;
                int r = u >> 3, tc = u & 7;
                uint32_t sw = SWZ(r * 128 + tc * 16);
                cp_async16(stg + sw, Abase + (size_t)r * D_DIM + nx * 64 + tc * 8);
                cp_async16(stg + 16384 + sw, Bbase + (size_t)r * D_DIM + nx * 64 + tc * 8);
            }
        }
        CP_COMMIT();
    }

    // ---- epilogue: hyperbolic distance + direct (i,j) store ----
    float sqi[2][2], rfi[2][2];
#pragma unroll
    for (int t = 0; t < 2; ++t)
#pragma unroll
        for (int g = 0; g < 2; ++g) {
            int r = i0 + wm * 32 + t * 16 + g * 8 + (lane >> 2);
            sqi[t][g] = g_sq[b * N_DIM + r];
            rfi[t][g] = 2.0f * g_inv[b * N_DIM + r];
        }
    const float* sqj  = g_sq  + b * N_DIM + j0;
    const float* invj = g_inv + b * N_DIM + j0;

#pragma unroll
    for (int u = 0; u < 4; ++u) {
        const int col = wn * 32 + u * 8 + (lane & 3) * 2;
        const float sq0 = __ldg(sqj + col),  sq1 = __ldg(sqj + col + 1);
        const float iv0 = __ldg(invj + col), iv1 = __ldg(invj + col + 1);
#pragma unroll
        for (int t = 0; t < 2; ++t)
#pragma unroll
            for (int g = 0; g < 2; ++g) {
                const int row = wm * 32 + t * 16 + g * 8 + (lane >> 2);
                const int ig = i0 + row;
                float d0 = hypd(acc[t][u][g * 2 + 0], sqi[t][g], rfi[t][g], sq0, iv0);
                float d1 = hypd(acc[t][u][g * 2 + 1], sqi[t][g], rfi[t][g], sq1, iv1);
                if (ig == j0 + col)     d0 = 0.0f;   // exact diagonal
                if (ig == j0 + col + 1) d1 = 0.0f;
                *reinterpret_cast<float2*>(
                    out + ((size_t)(b * N_DIM) + ig) * N_DIM + j0 + col) =
                    make_float2(d0, d1);
                acc[t][u][g * 2 + 0] = d0;           // keep for transpose pass
                acc[t][u][g * 2 + 1] = d1;
            }
    }

    // ---- transpose store for off-diagonal pairs: out[j,i] = D^T ----
    if (ti != tj) {
        float* S = reinterpret_cast<float*>(smem);   // 32 x 132 fp32 (reuses stage 0)
#pragma unroll
        for (int w = 0; w < 4; ++w) {
            __syncthreads();
            if (wn == w) {
#pragma unroll
                for (int t = 0; t < 2; ++t)
#pragma unroll
                    for (int u = 0; u < 4; ++u)
#pragma unroll
                        for (int g = 0; g < 2; ++g) {
                            const int r = wm * 32 + t * 16 + g * 8 + (lane >> 2);
                            const int c2 = u * 8 + (lane & 3) * 2;
                            S[c2 * 132 + r]       = acc[t][u][g * 2 + 0];
                            S[(c2 + 1) * 132 + r] = acc[t][u][g * 2 + 1];
                        }
            }
            __syncthreads();
            // store 32 rows (cols j0+w*32..+31 of D) x 128 floats, coalesced
#pragma unroll
            for (int k = 0; k < 2; ++k) {
                int idx = tid + k * 512;         // 1024 float4s
                int cc = idx >> 5, f4 = idx & 31;
                float4 v = *reinterpret_cast<const float4*>(S + cc * 132 + f4 * 4);
                *reinterpret_cast<float4*>(
                    out + ((size_t)(b * N_DIM) + j0 + w * 32 + cc) * N_DIM + i0 + f4 * 4) = v;
            }
        }
    }
}

// ============================================================================
// Launch
// ============================================================================
extern "C" void kernel_launch(void* const* d_in, const int* in_sizes, int n_in,
                              void* d_out, int out_size) {
    (void)in_sizes; (void)n_in; (void)out_size;
    const float* emb = (const float*)d_in[0];
    float* out = (float*)d_out;
    cudaFuncSetAttribute(hyp_main, cudaFuncAttributeMaxDynamicSharedMemorySize, SMEM_BYTES);
    hyp_prep<<<(B_DIM * N_DIM) / 8, 256>>>(emb);
    hyp_main<<<NCTA, 512, SMEM_BYTES>>>(out);
}

// round 7
// speedup vs baseline: 2.1715x; 1.0793x over previous
#include <cuda_runtime.h>
#include <cuda_bf16.h>
#include <cstdint>

// ============================================================================
// Problem constants
// ============================================================================
#define B_DIM 8
#define N_DIM 4096
#define D_DIM 512
#define TILE  128
#define NTILE (N_DIM / TILE)            // 32
#define PAIRS ((NTILE * (NTILE + 1)) / 2)  // 528 upper-triangular tile pairs
#define NCTA  (B_DIM * PAIRS)           // 4224 CTAs
#define NCHUNK 8                        // 512 / 64 K-chunks
#define PD 4                            // cp.async stages (A+B per stage)

// SMEM: 4 stages x (16KB A + 16KB B) = 128KB.
// Transpose scratch: 128 x 132 fp32 = 67.5KB, reuses stages 0-2 (the last
// K-chunk (7) lives in stage 3 at offset 96KB, disjoint from the scratch).
#define STAGE_BYTES 32768
#define SMEM_BYTES (PD * STAGE_BYTES)   // 131072

// Scratch (device globals — no cudaMalloc allowed)
__device__ __align__(16) __nv_bfloat16 g_xb[(size_t)B_DIM * N_DIM * D_DIM]; // 32 MB
__device__ float g_sq[B_DIM * N_DIM];
__device__ float g_inv[B_DIM * N_DIM];

// ============================================================================
// Helpers (base sm_103-safe PTX only: cp.async, ldmatrix, mma.sync)
// ============================================================================
__device__ __forceinline__ uint32_t smem_to_u32(const void* p) {
    uint32_t a;
    asm("{ .reg .u64 t; cvta.to.shared.u64 t, %1; cvt.u32.u64 %0, t; }" : "=r"(a) : "l"(p));
    return a;
}
#define SWZ(o) ((o) ^ (((o) >> 3) & 0x70))

__device__ __forceinline__ void cp_async16(uint32_t smem_addr, const void* gptr) {
    asm volatile("cp.async.cg.shared.global [%0], [%1], 16;" :: "r"(smem_addr), "l"(gptr) : "memory");
}
#define CP_COMMIT() asm volatile("cp.async.commit_group;" ::: "memory")
#define CP_WAIT2()  asm volatile("cp.async.wait_group 2;" ::: "memory")

__device__ __forceinline__ void ldm_x4(uint32_t* r, uint32_t addr) {
    asm volatile("ldmatrix.sync.aligned.m8n8.x4.shared.b16 {%0,%1,%2,%3}, [%4];"
                 : "=r"(r[0]), "=r"(r[1]), "=r"(r[2]), "=r"(r[3]) : "r"(addr));
}

__device__ __forceinline__ void mma16816(float* d, const uint32_t* a, const uint32_t* bq) {
    asm volatile(
        "mma.sync.aligned.m16n8k16.row.col.f32.bf16.bf16.f32 "
        "{%0,%1,%2,%3}, {%4,%5,%6,%7}, {%8,%9}, {%0,%1,%2,%3};"
        : "+f"(d[0]), "+f"(d[1]), "+f"(d[2]), "+f"(d[3])
        : "r"(a[0]), "r"(a[1]), "r"(a[2]), "r"(a[3]), "r"(bq[0]), "r"(bq[1]));
}

// Hyperbolic distance epilogue math (sqrt/lg2 via MUFU approx)
__device__ __forceinline__ float hypd(float gv, float sq_i, float rf_i, float sq_j, float inv_j) {
    float d2 = fmaf(-2.0f, gv, sq_i + sq_j);
    d2 = fmaxf(d2, 0.0f);
    float sd; asm("sqrt.approx.f32 %0, %1;" : "=f"(sd) : "f"(d2));
    float y   = sd * inv_j * rf_i;          // rf_i = 2 / (1 - ||x_i||^2)
    float arg = y + 1.0f;
    float t2  = fmaf(arg, arg, -1.0f);
    t2 = fmaxf(t2, 0.0f);
    float st; asm("sqrt.approx.f32 %0, %1;" : "=f"(st) : "f"(t2));
    float u = arg + st;
    float lg; asm("lg2.approx.f32 %0, %1;" : "=f"(lg) : "f"(u));
    return lg * 0.69314718055994531f;       // acosh(arg)
}

// ============================================================================
// Prep: fp32 -> bf16, per-row ||x||^2 and 1/(1-||x||^2).
// (inputs are in (-0.04,0.04): ||x|| <= 0.905 < 1, so __proj is identity)
// ============================================================================
__global__ void __launch_bounds__(256) hyp_prep(const float* __restrict__ emb) {
    const int rowid = blockIdx.x * 8 + (threadIdx.x >> 5);
    const int lane = threadIdx.x & 31;
    const float* src = emb + (size_t)rowid * D_DIM;
    __nv_bfloat16* dst = g_xb + (size_t)rowid * D_DIM;
    float ss = 0.0f;
#pragma unroll
    for (int k = 0; k < 4; ++k) {
        float4 v = reinterpret_cast<const float4*>(src)[lane + k * 32];
        ss = fmaf(v.x, v.x, ss); ss = fmaf(v.y, v.y, ss);
        ss = fmaf(v.z, v.z, ss); ss = fmaf(v.w, v.w, ss);
        union { __nv_bfloat162 h[2]; uint2 u; } cv;
        cv.h[0] = __floats2bfloat162_rn(v.x, v.y);
        cv.h[1] = __floats2bfloat162_rn(v.z, v.w);
        *reinterpret_cast<uint2*>(dst + lane * 4 + k * 128) = cv.u;
    }
#pragma unroll
    for (int o = 16; o > 0; o >>= 1) ss += __shfl_xor_sync(0xFFFFFFFFu, ss, o);
    if (lane == 0) {
        g_sq[rowid] = ss;
        g_inv[rowid] = 1.0f / (1.0f - ss);
    }
}

// ============================================================================
// Main: one CTA per (batch, upper-triangular 128x128 tile pair).
// 16 warps (4x4 grid), warp tile 32x32, mma.sync m16n8k16 bf16.
// 4-stage cp.async pipeline (prefill 3, one-stage gap => loads overlap MMA,
// single __syncthreads per chunk). Writes tile and its transpose.
// ============================================================================
__global__ void __launch_bounds__(512, 1) hyp_main(float* __restrict__ out) {
    extern __shared__ char smem[];
    const uint32_t sb = smem_to_u32(smem);
    const int tid  = threadIdx.x;
    const int lane = tid & 31;
    const int wid  = tid >> 5;
    const int wm   = wid >> 2;           // 0..3  (32-row slab)
    const int wn   = wid & 3;            // 0..3  (32-col slab)

    // ---- decode (batch, ti, tj) with ti <= tj ----
    const int bx = blockIdx.x;
    const int b  = bx / PAIRS;
    int p = bx - b * PAIRS;
    int ti = 0;
    while (p >= NTILE - ti) { p -= NTILE - ti; ++ti; }
    const int tj = ti + p;
    const int i0 = ti * TILE;
    const int j0 = tj * TILE;

    const __nv_bfloat16* Abase = g_xb + ((size_t)(b * N_DIM + i0)) * D_DIM;
    const __nv_bfloat16* Bbase = g_xb + ((size_t)(b * N_DIM + j0)) * D_DIM;

    // ---- prologue: prefill chunks 0..PD-2 (one stage kept free) ----
#pragma unroll
    for (int c = 0; c < PD - 1; ++c) {
#pragma unroll
        for (int it = 0; it < 2; ++it) {
            int u = tid + it * 512;      // 1024 16B units per operand chunk
            int r = u >> 3, tc = u & 7;
            uint32_t sw = SWZ(r * 128 + tc * 16);
            cp_async16(sb + c * STAGE_BYTES + sw,
                       Abase + (size_t)r * D_DIM + c * 64 + tc * 8);
            cp_async16(sb + c * STAGE_BYTES + 16384 + sw,
                       Bbase + (size_t)r * D_DIM + c * 64 + tc * 8);
        }
        CP_COMMIT();
    }

    float acc[2][4][4];
#pragma unroll
    for (int t = 0; t < 2; ++t)
#pragma unroll
        for (int u = 0; u < 4; ++u)
#pragma unroll
            for (int r = 0; r < 4; ++r) acc[t][u][r] = 0.0f;

    // ldmatrix addressing (validated mapping)
    int rowA[2], swA[2];
#pragma unroll
    for (int t = 0; t < 2; ++t) {
        rowA[t] = wm * 32 + t * 16 + (lane & 7) + ((lane >> 3) & 1) * 8;
        swA[t]  = (rowA[t] & 7) << 4;
    }
    int rowB[2], swB[2];
#pragma unroll
    for (int u2 = 0; u2 < 2; ++u2) {
        rowB[u2] = wn * 32 + u2 * 16 + (lane & 7) + (lane >> 4) * 8;
        swB[u2]  = (rowB[u2] & 7) << 4;
    }
    const int kaoff = (lane >> 4) * 16;
    const int kboff = ((lane >> 3) & 1) * 16;

    // ---- K loop: 8 chunks of 64; loads for c+PD-1 issued BEFORE MMA on c ----
    for (int c = 0; c < NCHUNK; ++c) {
        CP_WAIT2();            // chunk c resident (<=2 newer groups pending)
        __syncthreads();       // all warps past chunk c-1's MMA -> its stage free

        const int nx = c + PD - 1;
        if (nx < NCHUNK) {
            const uint32_t stg = sb + (nx % PD) * STAGE_BYTES;
#pragma unroll
            for (int it = 0; it < 2; ++it) {
                int u = tid + it * 512;
                int r = u >> 3, tc = u & 7;
                uint32_t sw = SWZ(r * 128 + tc * 16);
                cp_async16(stg + sw, Abase + (size_t)r * D_DIM + nx * 64 + tc * 8);
                cp_async16(stg + 16384 + sw, Bbase + (size_t)r * D_DIM + nx * 64 + tc * 8);
            }
        }
        CP_COMMIT();           // always commit to keep wait_group counts aligned

        const uint32_t ast = sb + (c % PD) * STAGE_BYTES;
        const uint32_t bst = ast + 16384;
#pragma unroll
        for (int s = 0; s < 4; ++s) {
            const int kb = s * 32;
            uint32_t afr[2][4];
#pragma unroll
            for (int t = 0; t < 2; ++t)
                ldm_x4(afr[t], ast + rowA[t] * 128 + ((kb + kaoff) ^ swA[t]));
            uint32_t bfr[2][4];
#pragma unroll
            for (int u2 = 0; u2 < 2; ++u2)
                ldm_x4(bfr[u2], bst + rowB[u2] * 128 + ((kb + kboff) ^ swB[u2]));
#pragma unroll
            for (int t = 0; t < 2; ++t)
#pragma unroll
                for (int u = 0; u < 4; ++u)
                    mma16816(acc[t][u], afr[t], &bfr[u >> 1][(u & 1) * 2]);
        }
    }

    // ---- epilogue: hyperbolic distance + direct (i,j) store ----
    float sqi[2][2], rfi[2][2];
#pragma unroll
    for (int t = 0; t < 2; ++t)
#pragma unroll
        for (int g = 0; g < 2; ++g) {
            int r = i0 + wm * 32 + t * 16 + g * 8 + (lane >> 2);
            sqi[t][g] = g_sq[b * N_DIM + r];
            rfi[t][g] = 2.0f * g_inv[b * N_DIM + r];
        }
    const float* sqj  = g_sq  + b * N_DIM + j0;
    const float* invj = g_inv + b * N_DIM + j0;

#pragma unroll
    for (int u = 0; u < 4; ++u) {
        const int col = wn * 32 + u * 8 + (lane & 3) * 2;
        const float sq0 = __ldg(sqj + col),  sq1 = __ldg(sqj + col + 1);
        const float iv0 = __ldg(invj + col), iv1 = __ldg(invj + col + 1);
#pragma unroll
        for (int t = 0; t < 2; ++t)
#pragma unroll
            for (int g = 0; g < 2; ++g) {
                const int row = wm * 32 + t * 16 + g * 8 + (lane >> 2);
                const int ig = i0 + row;
                float d0 = hypd(acc[t][u][g * 2 + 0], sqi[t][g], rfi[t][g], sq0, iv0);
                float d1 = hypd(acc[t][u][g * 2 + 1], sqi[t][g], rfi[t][g], sq1, iv1);
                if (ig == j0 + col)     d0 = 0.0f;   // exact diagonal
                if (ig == j0 + col + 1) d1 = 0.0f;
                *reinterpret_cast<float2*>(
                    out + ((size_t)(b * N_DIM) + ig) * N_DIM + j0 + col) =
                    make_float2(d0, d1);
                acc[t][u][g * 2 + 0] = d0;           // keep for transpose pass
                acc[t][u][g * 2 + 1] = d1;
            }
    }

    // ---- transpose store for off-diagonal pairs: out[j,i] = D^T ----
    // Full 128x132 fp32 scratch at smem+0 (stages 0-2). Safe: the last K-chunk
    // (7) maps to stage 3 at 96KB, so any warp still finishing chunk 7's MMA
    // reads a disjoint region.
    if (ti != tj) {
        float* S = reinterpret_cast<float*>(smem);
        // scatter: bank = (8*(lane&3) + (lane>>2)) mod 32 -> conflict-free
#pragma unroll
        for (int u = 0; u < 4; ++u) {
            const int c2 = wn * 32 + u * 8 + (lane & 3) * 2;
#pragma unroll
            for (int t = 0; t < 2; ++t)
#pragma unroll
                for (int g = 0; g < 2; ++g) {
                    const int r = wm * 32 + t * 16 + g * 8 + (lane >> 2);
                    S[c2 * 132 + r]       = acc[t][u][g * 2 + 0];
                    S[(c2 + 1) * 132 + r] = acc[t][u][g * 2 + 1];
                }
        }
        __syncthreads();
        // coalesced: 128 output rows x 128 floats = 4096 float4s / 512 thr
#pragma unroll
        for (int k = 0; k < 8; ++k) {
            int idx = tid + k * 512;
            int cc = idx >> 5, f4 = idx & 31;
            float4 v = *reinterpret_cast<const float4*>(S + cc * 132 + f4 * 4);
            *reinterpret_cast<float4*>(
                out + ((size_t)(b * N_DIM) + j0 + cc) * N_DIM + i0 + f4 * 4) = v;
        }
    }
}

// ============================================================================
// Launch
// ============================================================================
extern "C" void kernel_launch(void* const* d_in, const int* in_sizes, int n_in,
                              void* d_out, int out_size) {
    (void)in_sizes; (void)n_in; (void)out_size;
    const float* emb = (const float*)d_in[0];
    float* out = (float*)d_out;
    cudaFuncSetAttribute(hyp_main, cudaFuncAttributeMaxDynamicSharedMemorySize, SMEM_BYTES);
    hyp_prep<<<(B_DIM * N_DIM) / 8, 256>>>(emb);
    hyp_main<<<NCTA, 512, SMEM_BYTES>>>(out);
}

// round 8
// speedup vs baseline: 2.5362x; 1.1679x over previous
#include <cuda_runtime.h>
#include <cuda_bf16.h>
#include <cstdint>

// ============================================================================
// Problem constants
// ============================================================================
#define B_DIM 8
#define N_DIM 4096
#define D_DIM 512
#define TILE  128
#define NTILE (N_DIM / TILE)            // 32
#define PAIRS ((NTILE * (NTILE + 1)) / 2)  // 528 upper-triangular tile pairs
#define NCTA  (B_DIM * PAIRS)           // 4224 CTAs
#define NCHUNK 8                        // 512 / 64 K-chunks
#define PD 3                            // cp.async stages (A+B per stage)

// SMEM: 3 stages x (16KB A + 16KB B) = 96KB per CTA -> 2 CTAs/SM.
// Transpose scratch (128 x 132 fp32 = 67.5KB) reuses the stage region,
// guarded by a __syncthreads before the scatter.
#define STAGE_BYTES 32768
#define SMEM_BYTES (PD * STAGE_BYTES)   // 98304

// Scratch (device globals — no cudaMalloc allowed)
__device__ __align__(16) __nv_bfloat16 g_xb[(size_t)B_DIM * N_DIM * D_DIM]; // 32 MB
__device__ float g_sq[B_DIM * N_DIM];
__device__ float g_inv[B_DIM * N_DIM];

// ============================================================================
// Helpers (base sm_103-safe PTX only: cp.async, ldmatrix, mma.sync)
// ============================================================================
__device__ __forceinline__ uint32_t smem_to_u32(const void* p) {
    uint32_t a;
    asm("{ .reg .u64 t; cvta.to.shared.u64 t, %1; cvt.u32.u64 %0, t; }" : "=r"(a) : "l"(p));
    return a;
}
#define SWZ(o) ((o) ^ (((o) >> 3) & 0x70))

__device__ __forceinline__ void cp_async16(uint32_t smem_addr, const void* gptr) {
    asm volatile("cp.async.cg.shared.global [%0], [%1], 16;" :: "r"(smem_addr), "l"(gptr) : "memory");
}
#define CP_COMMIT() asm volatile("cp.async.commit_group;" ::: "memory")
#define CP_WAIT1()  asm volatile("cp.async.wait_group 1;" ::: "memory")

__device__ __forceinline__ void ldm_x4(uint32_t* r, uint32_t addr) {
    asm volatile("ldmatrix.sync.aligned.m8n8.x4.shared.b16 {%0,%1,%2,%3}, [%4];"
                 : "=r"(r[0]), "=r"(r[1]), "=r"(r[2]), "=r"(r[3]) : "r"(addr));
}

__device__ __forceinline__ void mma16816(float* d, const uint32_t* a, const uint32_t* bq) {
    asm volatile(
        "mma.sync.aligned.m16n8k16.row.col.f32.bf16.bf16.f32 "
        "{%0,%1,%2,%3}, {%4,%5,%6,%7}, {%8,%9}, {%0,%1,%2,%3};"
        : "+f"(d[0]), "+f"(d[1]), "+f"(d[2]), "+f"(d[3])
        : "r"(a[0]), "r"(a[1]), "r"(a[2]), "r"(a[3]), "r"(bq[0]), "r"(bq[1]));
}

// Hyperbolic distance epilogue math (sqrt/lg2 via MUFU approx)
__device__ __forceinline__ float hypd(float gv, float sq_i, float rf_i, float sq_j, float inv_j) {
    float d2 = fmaf(-2.0f, gv, sq_i + sq_j);
    d2 = fmaxf(d2, 0.0f);
    float sd; asm("sqrt.approx.f32 %0, %1;" : "=f"(sd) : "f"(d2));
    float y   = sd * inv_j * rf_i;          // rf_i = 2 / (1 - ||x_i||^2)
    float arg = y + 1.0f;
    float t2  = fmaf(arg, arg, -1.0f);
    t2 = fmaxf(t2, 0.0f);
    float st; asm("sqrt.approx.f32 %0, %1;" : "=f"(st) : "f"(t2));
    float u = arg + st;
    float lg; asm("lg2.approx.f32 %0, %1;" : "=f"(lg) : "f"(u));
    return lg * 0.69314718055994531f;       // acosh(arg)
}

// ============================================================================
// Prep: fp32 -> bf16, per-row ||x||^2 and 1/(1-||x||^2).
// (inputs are in (-0.04,0.04): ||x|| <= 0.905 < 1, so __proj is identity)
// ============================================================================
__global__ void __launch_bounds__(256) hyp_prep(const float* __restrict__ emb) {
    const int rowid = blockIdx.x * 8 + (threadIdx.x >> 5);
    const int lane = threadIdx.x & 31;
    const float* src = emb + (size_t)rowid * D_DIM;
    __nv_bfloat16* dst = g_xb + (size_t)rowid * D_DIM;
    float ss = 0.0f;
#pragma unroll
    for (int k = 0; k < 4; ++k) {
        float4 v = reinterpret_cast<const float4*>(src)[lane + k * 32];
        ss = fmaf(v.x, v.x, ss); ss = fmaf(v.y, v.y, ss);
        ss = fmaf(v.z, v.z, ss); ss = fmaf(v.w, v.w, ss);
        union { __nv_bfloat162 h[2]; uint2 u; } cv;
        cv.h[0] = __floats2bfloat162_rn(v.x, v.y);
        cv.h[1] = __floats2bfloat162_rn(v.z, v.w);
        *reinterpret_cast<uint2*>(dst + lane * 4 + k * 128) = cv.u;
    }
#pragma unroll
    for (int o = 16; o > 0; o >>= 1) ss += __shfl_xor_sync(0xFFFFFFFFu, ss, o);
    if (lane == 0) {
        g_sq[rowid] = ss;
        g_inv[rowid] = 1.0f / (1.0f - ss);
    }
}

// ============================================================================
// Main: one CTA per (batch, upper-triangular 128x128 tile pair).
// 256 threads, 8 warps (4x2 grid), warp tile 32x64 (6 B smem traffic / elem).
// 3-stage cp.async pipeline, 2 CTAs co-resident per SM so one CTA's MMA
// overlaps the other's MUFU/store epilogue. Writes tile and its transpose.
// ============================================================================
__global__ void __launch_bounds__(256, 2) hyp_main(float* __restrict__ out) {
    extern __shared__ char smem[];
    const uint32_t sb = smem_to_u32(smem);
    const int tid  = threadIdx.x;
    const int lane = tid & 31;
    const int wid  = tid >> 5;
    const int wm   = wid >> 1;           // 0..3  (32-row slab)
    const int wn   = wid & 1;            // 0..1  (64-col slab)

    // ---- decode (batch, ti, tj) with ti <= tj ----
    const int bx = blockIdx.x;
    const int b  = bx / PAIRS;
    int p = bx - b * PAIRS;
    int ti = 0;
    while (p >= NTILE - ti) { p -= NTILE - ti; ++ti; }
    const int tj = ti + p;
    const int i0 = ti * TILE;
    const int j0 = tj * TILE;

    const __nv_bfloat16* Abase = g_xb + ((size_t)(b * N_DIM + i0)) * D_DIM;
    const __nv_bfloat16* Bbase = g_xb + ((size_t)(b * N_DIM + j0)) * D_DIM;

    // ---- prologue: prefill chunks 0..PD-2 (one stage kept free) ----
#pragma unroll
    for (int c = 0; c < PD - 1; ++c) {
#pragma unroll
        for (int it = 0; it < 4; ++it) {
            int u = tid + it * 256;      // 1024 16B units per operand chunk
            int r = u >> 3, tc = u & 7;
            uint32_t sw = SWZ(r * 128 + tc * 16);
            cp_async16(sb + c * STAGE_BYTES + sw,
                       Abase + (size_t)r * D_DIM + c * 64 + tc * 8);
            cp_async16(sb + c * STAGE_BYTES + 16384 + sw,
                       Bbase + (size_t)r * D_DIM + c * 64 + tc * 8);
        }
        CP_COMMIT();
    }

    float acc[2][8][4];
#pragma unroll
    for (int t = 0; t < 2; ++t)
#pragma unroll
        for (int u = 0; u < 8; ++u)
#pragma unroll
            for (int r = 0; r < 4; ++r) acc[t][u][r] = 0.0f;

    // ldmatrix addressing (validated 32x64 mapping from the round-5 kernel)
    int rowA[2], swA[2];
#pragma unroll
    for (int t = 0; t < 2; ++t) {
        rowA[t] = wm * 32 + t * 16 + (lane & 7) + ((lane >> 3) & 1) * 8;
        swA[t]  = (rowA[t] & 7) << 4;
    }
    int rowB[4], swB[4];
#pragma unroll
    for (int u2 = 0; u2 < 4; ++u2) {
        rowB[u2] = wn * 64 + u2 * 16 + (lane & 7) + (lane >> 4) * 8;
        swB[u2]  = (rowB[u2] & 7) << 4;
    }
    const int kaoff = (lane >> 4) * 16;
    const int kboff = ((lane >> 3) & 1) * 16;

    // ---- K loop: 8 chunks of 64; loads for c+PD-1 issued BEFORE MMA on c ----
    for (int c = 0; c < NCHUNK; ++c) {
        CP_WAIT1();            // chunk c resident (<=1 newer group pending)
        __syncthreads();       // all warps past chunk c-1's MMA -> its stage free

        const int nx = c + PD - 1;
        if (nx < NCHUNK) {
            const uint32_t stg = sb + (nx % PD) * STAGE_BYTES;
#pragma unroll
            for (int it = 0; it < 4; ++it) {
                int u = tid + it * 256;
                int r = u >> 3, tc = u & 7;
                uint32_t sw = SWZ(r * 128 + tc * 16);
                cp_async16(stg + sw, Abase + (size_t)r * D_DIM + nx * 64 + tc * 8);
                cp_async16(stg + 16384 + sw, Bbase + (size_t)r * D_DIM + nx * 64 + tc * 8);
            }
        }
        CP_COMMIT();           // always commit to keep wait_group counts aligned

        const uint32_t ast = sb + (c % PD) * STAGE_BYTES;
        const uint32_t bst = ast + 16384;
#pragma unroll
        for (int s = 0; s < 4; ++s) {
            const int kb = s * 32;
            uint32_t afr[2][4];
#pragma unroll
            for (int t = 0; t < 2; ++t)
                ldm_x4(afr[t], ast + rowA[t] * 128 + ((kb + kaoff) ^ swA[t]));
            uint32_t bfr[4][4];
#pragma unroll
            for (int u2 = 0; u2 < 4; ++u2)
                ldm_x4(bfr[u2], bst + rowB[u2] * 128 + ((kb + kboff) ^ swB[u2]));
#pragma unroll
            for (int t = 0; t < 2; ++t)
#pragma unroll
                for (int u = 0; u < 8; ++u)
                    mma16816(acc[t][u], afr[t], &bfr[u >> 1][(u & 1) * 2]);
        }
    }

    // ---- epilogue: hyperbolic distance + direct (i,j) store ----
    float sqi[2][2], rfi[2][2];
#pragma unroll
    for (int t = 0; t < 2; ++t)
#pragma unroll
        for (int g = 0; g < 2; ++g) {
            int r = i0 + wm * 32 + t * 16 + g * 8 + (lane >> 2);
            sqi[t][g] = g_sq[b * N_DIM + r];
            rfi[t][g] = 2.0f * g_inv[b * N_DIM + r];
        }
    const float* sqj  = g_sq  + b * N_DIM + j0;
    const float* invj = g_inv + b * N_DIM + j0;

#pragma unroll
    for (int u = 0; u < 8; ++u) {
        const int col = wn * 64 + u * 8 + (lane & 3) * 2;
        const float sq0 = __ldg(sqj + col),  sq1 = __ldg(sqj + col + 1);
        const float iv0 = __ldg(invj + col), iv1 = __ldg(invj + col + 1);
#pragma unroll
        for (int t = 0; t < 2; ++t)
#pragma unroll
            for (int g = 0; g < 2; ++g) {
                const int row = wm * 32 + t * 16 + g * 8 + (lane >> 2);
                const int ig = i0 + row;
                float d0 = hypd(acc[t][u][g * 2 + 0], sqi[t][g], rfi[t][g], sq0, iv0);
                float d1 = hypd(acc[t][u][g * 2 + 1], sqi[t][g], rfi[t][g], sq1, iv1);
                if (ig == j0 + col)     d0 = 0.0f;   // exact diagonal
                if (ig == j0 + col + 1) d1 = 0.0f;
                *reinterpret_cast<float2*>(
                    out + ((size_t)(b * N_DIM) + ig) * N_DIM + j0 + col) =
                    make_float2(d0, d1);
                acc[t][u][g * 2 + 0] = d0;           // keep for transpose pass
                acc[t][u][g * 2 + 1] = d1;
            }
    }

    // ---- transpose store for off-diagonal pairs: out[j,i] = D^T ----
    // 128x132 fp32 scratch reuses the stage region; the sync ensures every
    // warp is done reading stage SMEM (chunk 7's MMA) before the scatter.
    if (ti != tj) {
        float* S = reinterpret_cast<float*>(smem);
        __syncthreads();
        // scatter: bank = (8*(lane&3) + (lane>>2)) mod 32 -> conflict-free
#pragma unroll
        for (int u = 0; u < 8; ++u) {
            const int c2 = wn * 64 + u * 8 + (lane & 3) * 2;
#pragma unroll
            for (int t = 0; t < 2; ++t)
#pragma unroll
                for (int g = 0; g < 2; ++g) {
                    const int r = wm * 32 + t * 16 + g * 8 + (lane >> 2);
                    S[c2 * 132 + r]       = acc[t][u][g * 2 + 0];
                    S[(c2 + 1) * 132 + r] = acc[t][u][g * 2 + 1];
                }
        }
        __syncthreads();
        // coalesced: 128 output rows x 128 floats = 4096 float4s / 256 thr
#pragma unroll
        for (int k = 0; k < 16; ++k) {
            int idx = tid + k * 256;
            int cc = idx >> 5, f4 = idx & 31;
            float4 v = *reinterpret_cast<const float4*>(S + cc * 132 + f4 * 4);
            *reinterpret_cast<float4*>(
                out + ((size_t)(b * N_DIM) + j0 + cc) * N_DIM + i0 + f4 * 4) = v;
        }
    }
}

// ============================================================================
// Launch
// ============================================================================
extern "C" void kernel_launch(void* const* d_in, const int* in_sizes, int n_in,
                              void* d_out, int out_size) {
    (void)in_sizes; (void)n_in; (void)out_size;
    const float* emb = (const float*)d_in[0];
    float* out = (float*)d_out;
    cudaFuncSetAttribute(hyp_main, cudaFuncAttributeMaxDynamicSharedMemorySize, SMEM_BYTES);
    hyp_prep<<<(B_DIM * N_DIM) / 8, 256>>>(emb);
    hyp_main<<<NCTA, 256, SMEM_BYTES>>>(out);
}